// round 17
// baseline (speedup 1.0000x reference)
#include <cuda_runtime.h>
#include <cstdint>

// ---------------------------------------------------------------------------
// out[8192,4096] = heaviside( (x/(||x||+1e-4)) @ W^T - 1 )
//
// Certified shortcut: ||x_norm|| = ||x||/(||x||+1e-4) < 1 strictly for all x;
// if max_j ||W_j||^2 < 0.96 then |h| < 0.98 < 1 everywhere and the output is
// identically zero. Certificate computed on-device every call (pure function
// of inputs -> deterministic, graph-safe).
//
// SINGLE persistent kernel, 1184 CTAs (co-resident by construction:
// <=32 regs via __launch_bounds__(256,8), 16KB smem, 2048 thr/SM;
// 1184 <= 8 x #SMs on both B300/148 and GB300/152):
//   phase A: R12's proven uniform 24KB-burst chunks (cert + zero-fill),
//            grid-strided over 8192 virtual chunks
//   grid barrier (monotonic-generation counter; no reset needed)
//   cert check (one __ldcg uint4 per thread) -> fast path: exit
//   fallback (never taken on this distribution): x norms -> barrier ->
//            fp32 smem-tiled GEMM + spike (correctness-only)
// ---------------------------------------------------------------------------

#define BDIM   8192
#define INDIM  4096
#define OUTDIM 4096

#define CERT_BOUND 0.96f
#define NROWCHUNK OUTDIM               // 4096 W-row chunks
#define NCHUNK 8192                    // total virtual chunks (24KB work each)
#define NB 1184                        // persistent CTAs = 148 x 8

__device__ __align__(16) unsigned char g_rowbad[NROWCHUNK];  // 1 byte per W row
__device__ float g_xscale[BDIM];                             // fallback only
__device__ unsigned int g_bar;                               // monotonic barrier

// ---------------------------------------------------------------------------
// grid barrier: monotonic generation counter, wrap-safe compare.
// All NB CTAs are co-resident (enforced by launch bounds + smem budget),
// so spinning is deadlock-free. Each executed barrier consumes exactly NB
// increments, so generations stay consistent across any number of launches.
// ---------------------------------------------------------------------------
__device__ __forceinline__ void grid_barrier(int t) {
    __threadfence();                    // publish this CTA's prior stores
    __syncthreads();
    if (t == 0) {
        unsigned old = atomicAdd(&g_bar, 1u);
        unsigned target = (old / NB + 1u) * NB;
        while ((int)(*(volatile unsigned*)&g_bar - target) < 0) { }
    }
    __syncthreads();
}

__global__ void __launch_bounds__(256, 8)
fused_kernel(const float* __restrict__ x, const float* __restrict__ W,
             float* __restrict__ out) {
    const int b = blockIdx.x;
    const int t = threadIdx.x;
    const float4 z = make_float4(0.0f, 0.0f, 0.0f, 0.0f);
    float4* o4 = reinterpret_cast<float4*>(out);
    __shared__ float ws[8];

    // ---- phase A: cert + zero-fill, R12 chunk layout, grid-stride ----
    for (int vb = b; vb < NCHUNK; vb += NB) {
        if (vb < NROWCHUNK) {
            // read W row vb: 1024 float4, 4/thread, contiguous
            const float4* wr = reinterpret_cast<const float4*>(W)
                             + (size_t)vb * (INDIM / 4);
            float4 v0 = wr[t], v1 = wr[t + 256], v2 = wr[t + 512], v3 = wr[t + 768];

            // zero 8KB slice of out[0 .. 32MB)
            float4* zb = o4 + (size_t)vb * 512;
            zb[t] = z;
            zb[t + 256] = z;

            float ss = v0.x*v0.x + v0.y*v0.y + v0.z*v0.z + v0.w*v0.w
                     + v1.x*v1.x + v1.y*v1.y + v1.z*v1.z + v1.w*v1.w
                     + v2.x*v2.x + v2.y*v2.y + v2.z*v2.z + v2.w*v2.w
                     + v3.x*v3.x + v3.y*v3.y + v3.z*v3.z + v3.w*v3.w;
            #pragma unroll
            for (int o = 16; o > 0; o >>= 1)
                ss += __shfl_xor_sync(0xFFFFFFFFu, ss, o);
            if ((t & 31) == 0) ws[t >> 5] = ss;
            __syncthreads();
            if (t == 0) {
                float tot = ws[0] + ws[1] + ws[2] + ws[3]
                          + ws[4] + ws[5] + ws[6] + ws[7];
                g_rowbad[vb] = (tot >= CERT_BOUND) ? 1u : 0u;
            }
            __syncthreads();
        } else {
            // zero 24KB slice of out[32MB ..)
            float4* zb = o4 + (size_t)(2 * 1024 * 1024)
                            + (size_t)(vb - NROWCHUNK) * 1536;
            #pragma unroll
            for (int j = 0; j < 6; j++)
                zb[t + j * 256] = z;
        }
    }

    // ---- barrier: all flag writes + zero stores globally visible ----
    grid_barrier(t);

    // ---- certificate check: 4096 bytes = 256 threads x one uint4 ----
    {
        uint4 v = __ldcg(reinterpret_cast<const uint4*>(g_rowbad) + t);
        int bad = __syncthreads_or((v.x | v.y | v.z | v.w) != 0u);
        if (!bad) return;               // certified: output is all zeros
    }

    // =======================================================================
    // Fallback (cert failed — unreachable for this input distribution).
    // Correctness-only fp32 path.
    // =======================================================================

    // x row norms -> g_xscale
    for (int row = b; row < BDIM; row += NB) {
        const float4* xr = reinterpret_cast<const float4*>(x)
                         + (size_t)row * (INDIM / 4);
        float4 v0 = xr[t], v1 = xr[t + 256], v2 = xr[t + 512], v3 = xr[t + 768];
        float ss = v0.x*v0.x + v0.y*v0.y + v0.z*v0.z + v0.w*v0.w
                 + v1.x*v1.x + v1.y*v1.y + v1.z*v1.z + v1.w*v1.w
                 + v2.x*v2.x + v2.y*v2.y + v2.z*v2.z + v2.w*v2.w
                 + v3.x*v3.x + v3.y*v3.y + v3.z*v3.z + v3.w*v3.w;
        #pragma unroll
        for (int o = 16; o > 0; o >>= 1)
            ss += __shfl_xor_sync(0xFFFFFFFFu, ss, o);
        if ((t & 31) == 0) ws[t >> 5] = ss;
        __syncthreads();
        if (t == 0) {
            float tot = ws[0] + ws[1] + ws[2] + ws[3]
                      + ws[4] + ws[5] + ws[6] + ws[7];
            g_xscale[row] = 1.0f / (sqrtf(tot) + 1e-4f);
        }
        __syncthreads();
    }

    grid_barrier(t);                    // norms visible before GEMM reads

    // fp32 smem-tiled GEMM: tiles 64x64, BK=32; 16x16 threads x (4x4 outputs)
    __shared__ float As[64 * 32];
    __shared__ float Bs[64 * 32];
    const int tx = t & 15, ty = t >> 4;
    const int NTIL = (BDIM / 64) * (OUTDIM / 64);   // 8192
    const int NUMN = OUTDIM / 64;                   // 64

    for (int tile = b; tile < NTIL; tile += NB) {
        const int m0 = (tile / NUMN) * 64;
        const int n0 = (tile % NUMN) * 64;

        float acc[4][4];
        #pragma unroll
        for (int i = 0; i < 4; i++)
            #pragma unroll
            for (int j = 0; j < 4; j++) acc[i][j] = 0.0f;

        for (int k0 = 0; k0 < INDIM; k0 += 32) {
            __syncthreads();
            // load A tile (x * scale) and B tile (W), coalesced
            for (int i = t; i < 64 * 32; i += 256) {
                int r = i >> 5, c = i & 31;
                float sc = __ldcg(&g_xscale[m0 + r]);
                As[i] = x[(size_t)(m0 + r) * INDIM + k0 + c] * sc;
                Bs[i] = W[(size_t)(n0 + r) * INDIM + k0 + c];
            }
            __syncthreads();
            #pragma unroll 8
            for (int kk = 0; kk < 32; kk++) {
                float a[4], bb[4];
                #pragma unroll
                for (int i = 0; i < 4; i++) a[i]  = As[(ty * 4 + i) * 32 + kk];
                #pragma unroll
                for (int j = 0; j < 4; j++) bb[j] = Bs[(tx * 4 + j) * 32 + kk];
                #pragma unroll
                for (int i = 0; i < 4; i++)
                    #pragma unroll
                    for (int j = 0; j < 4; j++)
                        acc[i][j] += a[i] * bb[j];
            }
        }

        #pragma unroll
        for (int i = 0; i < 4; i++) {
            size_t row = (size_t)(m0 + ty * 4 + i);
            #pragma unroll
            for (int j = 0; j < 4; j++)
                out[row * OUTDIM + n0 + tx * 4 + j] =
                    (acc[i][j] >= 1.0f) ? 1.0f : 0.0f;
        }
        __syncthreads();
    }
}

// ---------------------------------------------------------------------------
// Launch: ONE static launch; behavior a pure function of inputs.
// ---------------------------------------------------------------------------
extern "C" void kernel_launch(void* const* d_in, const int* in_sizes, int n_in,
                              void* d_out, int out_size) {
    const float* x = (const float*)d_in[0];
    const float* W = (const float*)d_in[1];
    float* out = (float*)d_out;

    fused_kernel<<<NB, 256>>>(x, W, out);
}